// round 17
// baseline (speedup 1.0000x reference)
#include <cuda_runtime.h>
#include <cuda_bf16.h>

#define NN 100000
#define EE 1600000
#define BB 256
#define NCH 98          // ceil(NN / 1024)
#define EBK 6250        // edge blocks (256 edges each)
#define XBK 1563        // xs blocks (NN*4/256)

// ---- scratch (device globals; zeroed at load; recycled via end-of-call cleanup) ----
__device__ __align__(128) float g_u[(size_t)NN * 64];             // aggregated features (fp32)
__device__ __align__(128) __nv_bfloat16 g_hb[(size_t)NN * 64];    // dis-scaled features (bf16)
__device__ __align__(128) float g_dis[NN];                        // rsqrt(deg+1)
__device__ int   g_deg[NN];     // in-degree   (zeroed by k_final for next call)
__device__ int   g_cur[NN];     // sort cursor (zeroed by k_final)
__device__ int   g_scan[NN];    // chunk-local inclusive scan
__device__ int   g_bsum[NCH];
__device__ int   g_boff[NCH];
__device__ int   g_esrc[EE];
__device__ int   g_tick;        // scan ticket (zeroed by k_final)
__device__ __align__(128) float g_sums[BB * 128];  // zeroed by launch 0
__device__ float g_cnt[BB];                        // zeroed by launch 0
__device__ int   g_is64;

__device__ __forceinline__ void red_add_v4(float* addr, float4 v) {
    unsigned long long ga = (unsigned long long)__cvta_generic_to_global(addr);
    asm volatile("red.global.add.v4.f32 [%0], {%1,%2,%3,%4};"
                 :: "l"(ga), "f"(v.x), "f"(v.y), "f"(v.z), "f"(v.w) : "memory");
}

// per-warp dtype detection: int64 storage of small ints -> odd 32-bit words all zero
__device__ __forceinline__ int detect64(const int* raw) {
    int lane = threadIdx.x & 31;
    int w = (lane < 16) ? raw[2 * lane + 1] : 0;
    return __ballot_sync(0xffffffffu, w != 0) == 0u;
}

__device__ __forceinline__ int load_idx64(const void* p, long long i, int is64) {
    return is64 ? (int)((const long long*)p)[i] : ((const int*)p)[i];
}

// accumulate 8 bf16 (one uint4) into 8 fp32 accumulators
__device__ __forceinline__ void acc8(float* acc, uint4 pk) {
    const __nv_bfloat162* b2 = reinterpret_cast<const __nv_bfloat162*>(&pk);
    #pragma unroll
    for (int j = 0; j < 4; j++) {
        float2 f2 = __bfloat1622float2(b2[j]);
        acc[j * 2 + 0] += f2.x;
        acc[j * 2 + 1] += f2.y;
    }
}

// pairwise bf16x2 add of two uint4 payloads (4x HADD2.BF16_V2)
__device__ __forceinline__ uint4 hadd2x4(uint4 a, uint4 b) {
    const __nv_bfloat162* a2 = reinterpret_cast<const __nv_bfloat162*>(&a);
    const __nv_bfloat162* b2 = reinterpret_cast<const __nv_bfloat162*>(&b);
    uint4 t;
    __nv_bfloat162* t2 = reinterpret_cast<__nv_bfloat162*>(&t);
    #pragma unroll
    for (int j = 0; j < 4; j++) t2[j] = __hadd2(a2[j], b2[j]);
    return t;
}

__device__ __forceinline__ uint4 pack8(const float* o) {
    __nv_bfloat162 q0 = __floats2bfloat162_rn(o[0], o[1]);
    __nv_bfloat162 q1 = __floats2bfloat162_rn(o[2], o[3]);
    __nv_bfloat162 q2 = __floats2bfloat162_rn(o[4], o[5]);
    __nv_bfloat162 q3 = __floats2bfloat162_rn(o[6], o[7]);
    uint4 pk;
    pk.x = *reinterpret_cast<unsigned*>(&q0);
    pk.y = *reinterpret_cast<unsigned*>(&q1);
    pk.z = *reinterpret_cast<unsigned*>(&q2);
    pk.w = *reinterpret_cast<unsigned*>(&q3);
    return pk;
}

// ---- launch 0: edge histogram + pool zero + is64 ----
__global__ void k_hist(const void* __restrict__ ei) {
    int e = blockIdx.x * 256 + threadIdx.x;
    int is64 = detect64((const int*)ei);
    if (e < BB * 128) g_sums[e] = 0.f;
    if (e < BB) g_cnt[e] = 0.f;
    if (e == 0) g_is64 = is64;
    if (e >= EE) return;
    int d = load_idx64(ei, (long long)EE + e, is64);
    if ((unsigned)d >= NN) d = 0;
    atomicAdd(&g_deg[d], 1);
}

// ---- launch 1: chunk scans + dis, last block scans chunk totals ----
__global__ void k_scan12() {
    __shared__ int s[1024];
    __shared__ int s2[128];
    __shared__ int slast;
    int t = threadIdx.x;
    int i = blockIdx.x * 1024 + t;
    int v = (i < NN) ? g_deg[i] : 0;
    if (i < NN) g_dis[i] = rsqrtf((float)v + 1.f);
    s[t] = v;
    __syncthreads();
    #pragma unroll
    for (int d = 1; d < 1024; d <<= 1) {
        int add = (t >= d) ? s[t - d] : 0;
        __syncthreads();
        s[t] += add;
        __syncthreads();
    }
    if (i < NN) g_scan[i] = s[t];
    if (t == 1023) g_bsum[blockIdx.x] = s[1023];
    __threadfence();
    __syncthreads();
    if (t == 0) slast = (atomicAdd(&g_tick, 1) == NCH - 1) ? 1 : 0;
    __syncthreads();
    if (slast) {
        __threadfence();
        int v2 = (t < NCH) ? g_bsum[t] : 0;
        if (t < 128) s2[t] = v2;
        __syncthreads();
        #pragma unroll
        for (int d = 1; d < 128; d <<= 1) {
            int add = (t >= d && t < 128) ? s2[t - d] : 0;
            __syncthreads();
            if (t < 128) s2[t] += add;
            __syncthreads();
        }
        if (t < NCH) g_boff[t] = s2[t] - v2;   // exclusive
    }
}

// ---- launch 2: counting-sort edges by dst  +  xs = dis*x (bf16, 22->32 pad) ----
__global__ void k_sortxs(const void* __restrict__ ei, const float* __restrict__ x) {
    int tid = threadIdx.x;
    if (blockIdx.x < EBK) {
        int e = blockIdx.x * 256 + tid;
        int is64 = detect64((const int*)ei);
        if (e >= EE) return;
        int sIdx = load_idx64(ei, e, is64);
        int d = load_idx64(ei, (long long)EE + e, is64);
        if ((unsigned)sIdx >= NN) sIdx = 0;
        if ((unsigned)d >= NN) d = 0;
        int off = g_boff[d >> 10] + g_scan[d] - g_deg[d];
        int p = off + atomicAdd(&g_cur[d], 1);
        g_esrc[p] = sIdx;
    } else {
        int j = (blockIdx.x - EBK) * 256 + tid;
        int n = j >> 2;
        if (n >= NN) return;
        int q = j & 3;
        float dis = g_dis[n];
        float o[8];
        #pragma unroll
        for (int k = 0; k < 8; k++) {
            int col = q * 8 + k;
            o[k] = (col < 22) ? dis * x[(size_t)n * 22 + col] : 0.f;
        }
        reinterpret_cast<uint4*>(g_hb)[(size_t)n * 4 + q] = pack8(o);
    }
}

// ---- aggregation: u[n] = sum_src hb[src] + hb[n]   (COLS/8 threads per node) ----
// 4-way unroll with pairwise bf16 tree-add: 2 HADD2x4 + 2 fp32 accumulates.
template <int COLS>
__global__ void k_agg() {
    constexpr int TPN = COLS / 8;
    int t = blockIdx.x * blockDim.x + threadIdx.x;
    int n = t / TPN;
    if (n >= NN) return;
    int c = t % TPN;
    int deg = g_deg[n];
    int off = g_boff[n >> 10] + g_scan[n] - deg;
    const uint4* hb = reinterpret_cast<const uint4*>(g_hb);
    float acc[8];
    {
        uint4 self = __ldg(&hb[(size_t)n * TPN + c]);
        const __nv_bfloat162* b2 = reinterpret_cast<const __nv_bfloat162*>(&self);
        #pragma unroll
        for (int j = 0; j < 4; j++) {
            float2 f2 = __bfloat1622float2(b2[j]);
            acc[j * 2 + 0] = f2.x;
            acc[j * 2 + 1] = f2.y;
        }
    }
    int p = off, end = off + deg;
    for (; p + 3 < end; p += 4) {
        int s0 = __ldg(&g_esrc[p]);
        int s1 = __ldg(&g_esrc[p + 1]);
        int s2 = __ldg(&g_esrc[p + 2]);
        int s3 = __ldg(&g_esrc[p + 3]);
        uint4 v0 = __ldg(&hb[(size_t)s0 * TPN + c]);
        uint4 v1 = __ldg(&hb[(size_t)s1 * TPN + c]);
        uint4 v2 = __ldg(&hb[(size_t)s2 * TPN + c]);
        uint4 v3 = __ldg(&hb[(size_t)s3 * TPN + c]);
        uint4 t01 = hadd2x4(v0, v1);     // pairwise bf16 tree level
        uint4 t23 = hadd2x4(v2, v3);
        acc8(acc, t01);
        acc8(acc, t23);
    }
    for (; p < end; p++) {
        int s0 = __ldg(&g_esrc[p]);
        uint4 v0 = __ldg(&hb[(size_t)s0 * TPN + c]);
        acc8(acc, v0);
    }
    size_t ob = (size_t)n * COLS + c * 8;
    *reinterpret_cast<float4*>(g_u + ob)     = make_float4(acc[0], acc[1], acc[2], acc[3]);
    *reinterpret_cast<float4*>(g_u + ob + 4) = make_float4(acc[4], acc[5], acc[6], acc[7]);
}

// ---- GEMM + BN/ReLU epilogue: hb = dis * relu(bn(dis*(u@W) + b)) as bf16 ----
// FIN=32 pads W (22 real rows); FIN=64 vector-loads W.
template <int FIN, int FOUT, int NPB, int WROWS>
__global__ void k_gemm_epi(const float* __restrict__ W, const float* __restrict__ b,
                           const float* __restrict__ g, const float* __restrict__ be,
                           const float* __restrict__ m, const float* __restrict__ v) {
    constexpr int FG = FOUT / 4, RS = 256 / FG, RPT = NPB / RS;
    __shared__ float sW[FIN * FOUT];
    __shared__ float sX[NPB * FIN];
    const int tid = threadIdx.x;
    for (int i = tid; i < FIN * FOUT; i += 256) {
        int k = i / FOUT;
        sW[i] = (k < WROWS) ? W[(size_t)k * FOUT + (i % FOUT)] : 0.f;
    }
    const int n0 = blockIdx.x * NPB;
    for (int i = tid; i < NPB * FIN / 4; i += 256) {
        int nn = i / (FIN / 4), k4 = i % (FIN / 4);
        int n = n0 + nn;
        reinterpret_cast<float4*>(sX)[i] = (n < NN)
            ? *reinterpret_cast<const float4*>(g_u + (size_t)n * FIN + k4 * 4)
            : make_float4(0.f, 0.f, 0.f, 0.f);
    }
    __syncthreads();
    const int fg = tid % FG, rs = tid / FG;
    float4 acc[RPT];
    #pragma unroll
    for (int r = 0; r < RPT; r++) acc[r] = make_float4(0.f, 0.f, 0.f, 0.f);
    #pragma unroll
    for (int k = 0; k < FIN; k++) {
        float4 w = *reinterpret_cast<const float4*>(&sW[k * FOUT + fg * 4]);
        #pragma unroll
        for (int r = 0; r < RPT; r++) {
            float xv = sX[(rs + r * RS) * FIN + k];
            acc[r].x = fmaf(xv, w.x, acc[r].x);
            acc[r].y = fmaf(xv, w.y, acc[r].y);
            acc[r].z = fmaf(xv, w.z, acc[r].z);
            acc[r].w = fmaf(xv, w.w, acc[r].w);
        }
    }
    int f = fg * 4;
    float4 bb  = *reinterpret_cast<const float4*>(b + f);
    float4 gg  = *reinterpret_cast<const float4*>(g + f);
    float4 bee = *reinterpret_cast<const float4*>(be + f);
    float4 mm  = *reinterpret_cast<const float4*>(m + f);
    float4 vv  = *reinterpret_cast<const float4*>(v + f);
    float4 sc;
    sc.x = gg.x * rsqrtf(vv.x + 1e-5f);
    sc.y = gg.y * rsqrtf(vv.y + 1e-5f);
    sc.z = gg.z * rsqrtf(vv.z + 1e-5f);
    sc.w = gg.w * rsqrtf(vv.w + 1e-5f);
    #pragma unroll
    for (int r = 0; r < RPT; r++) {
        int n = n0 + rs + r * RS;
        if (n >= NN) continue;
        float dis = g_dis[n];
        float a0 = fmaxf((dis * acc[r].x + bb.x - mm.x) * sc.x + bee.x, 0.f) * dis;
        float a1 = fmaxf((dis * acc[r].y + bb.y - mm.y) * sc.y + bee.y, 0.f) * dis;
        float a2 = fmaxf((dis * acc[r].z + bb.z - mm.z) * sc.z + bee.z, 0.f) * dis;
        float a3 = fmaxf((dis * acc[r].w + bb.w - mm.w) * sc.w + bee.w, 0.f) * dis;
        __nv_bfloat162 q0 = __floats2bfloat162_rn(a0, a1);
        __nv_bfloat162 q1 = __floats2bfloat162_rn(a2, a3);
        uint2 pk;
        pk.x = *reinterpret_cast<unsigned*>(&q0);
        pk.y = *reinterpret_cast<unsigned*>(&q1);
        *reinterpret_cast<uint2*>(g_hb + (size_t)n * FOUT + f) = pk;
    }
}

// ---- layer-3 GEMM + ReLU + mean-pool epilogue (64 -> 128) ----
__global__ void k_gemm_pool(const float* __restrict__ W, const float* __restrict__ b3,
                            const void* __restrict__ batch) {
    constexpr int FIN = 64, FOUT = 128, NPB = 16;
    constexpr int FG = FOUT / 4, RS = 256 / FG, RPT = NPB / RS;   // 32, 8, 2
    __shared__ float sW[FIN * FOUT];
    __shared__ float sX[NPB * FIN];
    const int tid = threadIdx.x;
    for (int i = tid; i < FIN * FOUT / 4; i += 256)
        reinterpret_cast<float4*>(sW)[i] = reinterpret_cast<const float4*>(W)[i];
    const int n0 = blockIdx.x * NPB;
    for (int i = tid; i < NPB * FIN / 4; i += 256) {
        int nn = i / (FIN / 4), k4 = i % (FIN / 4);
        int n = n0 + nn;
        reinterpret_cast<float4*>(sX)[i] = (n < NN)
            ? *reinterpret_cast<const float4*>(g_u + (size_t)n * FIN + k4 * 4)
            : make_float4(0.f, 0.f, 0.f, 0.f);
    }
    __syncthreads();
    const int fg = tid % FG, rs = tid / FG;
    float4 acc[RPT];
    #pragma unroll
    for (int r = 0; r < RPT; r++) acc[r] = make_float4(0.f, 0.f, 0.f, 0.f);
    #pragma unroll
    for (int k = 0; k < FIN; k++) {
        float4 w = *reinterpret_cast<const float4*>(&sW[k * FOUT + fg * 4]);
        #pragma unroll
        for (int r = 0; r < RPT; r++) {
            float xv = sX[(rs + r * RS) * FIN + k];
            acc[r].x = fmaf(xv, w.x, acc[r].x);
            acc[r].y = fmaf(xv, w.y, acc[r].y);
            acc[r].z = fmaf(xv, w.z, acc[r].z);
            acc[r].w = fmaf(xv, w.w, acc[r].w);
        }
    }
    int f = fg * 4;
    float4 bb = *reinterpret_cast<const float4*>(b3 + f);
    int is64 = g_is64;
    #pragma unroll
    for (int r = 0; r < RPT; r++) {
        int n = n0 + rs + r * RS;
        if (n >= NN) continue;
        float dis = g_dis[n];
        float4 o;
        o.x = fmaxf(dis * acc[r].x + bb.x, 0.f);
        o.y = fmaxf(dis * acc[r].y + bb.y, 0.f);
        o.z = fmaxf(dis * acc[r].z + bb.z, 0.f);
        o.w = fmaxf(dis * acc[r].w + bb.w, 0.f);
        int bg = load_idx64(batch, n, is64);
        if ((unsigned)bg >= BB) bg = 0;
        red_add_v4(g_sums + bg * 128 + f, o);
        if (fg == 0) atomicAdd(&g_cnt[bg], 1.f);
    }
}

// ---- finalize + cleanup for next call ----
__global__ void k_final(float* __restrict__ out) {
    int i = blockIdx.x * blockDim.x + threadIdx.x;
    if (i < BB * 128) out[i] = g_sums[i] / fmaxf(g_cnt[i >> 7], 1.f);
    if (i < NN) { g_deg[i] = 0; g_cur[i] = 0; }
    if (i == 0) g_tick = 0;
}

extern "C" void kernel_launch(void* const* d_in, const int* in_sizes, int n_in,
                              void* d_out, int out_size) {
    const float* x   = (const float*)d_in[0];
    const void*  ei  = d_in[1];
    const void*  bat = d_in[2];
    const float* W1 = (const float*)d_in[3];
    const float* b1 = (const float*)d_in[4];
    const float* W2 = (const float*)d_in[5];
    const float* b2 = (const float*)d_in[6];
    const float* W3 = (const float*)d_in[7];
    const float* b3 = (const float*)d_in[8];
    const float* g1 = (const float*)d_in[9];
    const float* be1 = (const float*)d_in[10];
    const float* m1 = (const float*)d_in[11];
    const float* v1 = (const float*)d_in[12];
    const float* g2 = (const float*)d_in[13];
    const float* be2 = (const float*)d_in[14];
    const float* m2 = (const float*)d_in[15];
    const float* v2 = (const float*)d_in[16];

    const int TB = 256;

    k_hist<<<EBK, TB>>>(ei);                                     // 0
    k_scan12<<<NCH, 1024>>>();                                   // 1
    k_sortxs<<<EBK + XBK, TB>>>(ei, x);                          // 2
    k_agg<32><<<(NN * 4 + TB - 1) / TB, TB>>>();                 // 3 <- profiled
    k_gemm_epi<32, 64, 32, 22><<<(NN + 31) / 32, TB>>>(W1, b1, g1, be1, m1, v1);  // 4
    k_agg<64><<<(NN * 8 + TB - 1) / TB, TB>>>();                 // 5
    k_gemm_epi<64, 64, 32, 64><<<(NN + 31) / 32, TB>>>(W2, b2, g2, be2, m2, v2);  // 6
    k_agg<64><<<(NN * 8 + TB - 1) / TB, TB>>>();                 // 7
    k_gemm_pool<<<(NN + 15) / 16, TB>>>(W3, b3, bat);            // 8
    k_final<<<(NN + TB - 1) / TB, TB>>>((float*)d_out);          // 9
}